// round 2
// baseline (speedup 1.0000x reference)
#include <cuda_runtime.h>
#include <mma.h>
using namespace nvcuda;

#define NNODES 2048   // B*N
#define HD     768
#define NHEADS 12
#define DHEAD  64
#define DEG    32
#define NPB    256    // nodes per batch (N)

// Scratch for projections (no cudaMalloc allowed)
__device__ float g_Q[NNODES * HD];
__device__ float g_K[NNODES * HD];
__device__ float g_V[NNODES * HD];

// ---------------------------------------------------------------------------
// Kernel 1: QKV projection GEMM, C = X @ W + b   (tf32 wmma, fp32 accumulate)
// X: (2048, 768) row-major, W: (768, 768) row-major. grid.z selects Q/K/V.
// Block tile 64x64, BK=32, 4 warps each owning a 32x32 subtile (2x2 frags).
// ---------------------------------------------------------------------------
#define BM 64
#define BN 64
#define BK 32

__global__ __launch_bounds__(128) void qkv_gemm(
    const float* __restrict__ X,
    const float* __restrict__ Wq, const float* __restrict__ bq,
    const float* __restrict__ Wk, const float* __restrict__ bk,
    const float* __restrict__ Wv, const float* __restrict__ bv)
{
    const int z = blockIdx.z;
    const float* W    = (z == 0) ? Wq : (z == 1) ? Wk : Wv;
    const float* bias = (z == 0) ? bq : (z == 1) ? bk : bv;
    float* C          = (z == 0) ? g_Q : (z == 1) ? g_K : g_V;

    __shared__ __align__(16) float As[BM][36];   // 64x32 data, stride 36 (144B, 16B-mult)
    __shared__ __align__(16) float Bs[BK][68];   // 32x64 data, stride 68 (272B, 16B-mult)
    __shared__ __align__(16) float Cs[BM][68];

    const int tid  = threadIdx.x;
    const int warp = tid >> 5;
    const int wm   = (warp >> 1) * 32;
    const int wn   = (warp & 1) * 32;
    const int rowBase = blockIdx.x * BM;
    const int colBase = blockIdx.y * BN;

    wmma::fragment<wmma::accumulator, 16, 16, 8, float> cf[2][2];
    #pragma unroll
    for (int i = 0; i < 2; i++)
        #pragma unroll
        for (int j = 0; j < 2; j++)
            wmma::fill_fragment(cf[i][j], 0.0f);

    for (int k0 = 0; k0 < HD; k0 += BK) {
        // Load A tile (64x32): 512 float4, 4 per thread
        #pragma unroll
        for (int q = 0; q < 4; q++) {
            int idx = tid + 128 * q;
            int m = idx >> 3, c = idx & 7;
            *(float4*)&As[m][4 * c] =
                *(const float4*)&X[(size_t)(rowBase + m) * HD + k0 + 4 * c];
        }
        // Load B tile (32x64): 512 float4, 4 per thread
        #pragma unroll
        for (int q = 0; q < 4; q++) {
            int idx = tid + 128 * q;
            int kk = idx >> 4, c = idx & 15;
            *(float4*)&Bs[kk][4 * c] =
                *(const float4*)&W[(size_t)(k0 + kk) * HD + colBase + 4 * c];
        }
        __syncthreads();

        #pragma unroll
        for (int kk = 0; kk < BK; kk += 8) {
            wmma::fragment<wmma::matrix_a, 16, 16, 8, wmma::precision::tf32, wmma::row_major> a0, a1;
            wmma::fragment<wmma::matrix_b, 16, 16, 8, wmma::precision::tf32, wmma::row_major> b0, b1;
            wmma::load_matrix_sync(a0, &As[wm][kk], 36);
            wmma::load_matrix_sync(a1, &As[wm + 16][kk], 36);
            wmma::load_matrix_sync(b0, &Bs[kk][wn], 68);
            wmma::load_matrix_sync(b1, &Bs[kk][wn + 16], 68);
            #pragma unroll
            for (int t = 0; t < a0.num_elements; t++) {
                a0.x[t] = wmma::__float_to_tf32(a0.x[t]);
                a1.x[t] = wmma::__float_to_tf32(a1.x[t]);
            }
            #pragma unroll
            for (int t = 0; t < b0.num_elements; t++) {
                b0.x[t] = wmma::__float_to_tf32(b0.x[t]);
                b1.x[t] = wmma::__float_to_tf32(b1.x[t]);
            }
            wmma::mma_sync(cf[0][0], a0, b0, cf[0][0]);
            wmma::mma_sync(cf[0][1], a0, b1, cf[0][1]);
            wmma::mma_sync(cf[1][0], a1, b0, cf[1][0]);
            wmma::mma_sync(cf[1][1], a1, b1, cf[1][1]);
        }
        __syncthreads();
    }

    // Epilogue: stage to smem, add bias, write out
    #pragma unroll
    for (int i = 0; i < 2; i++)
        #pragma unroll
        for (int j = 0; j < 2; j++)
            wmma::store_matrix_sync(&Cs[wm + 16 * i][wn + 16 * j], cf[i][j], 68,
                                    wmma::mem_row_major);
    __syncthreads();
    #pragma unroll
    for (int q = 0; q < 8; q++) {
        int idx = tid + 128 * q;
        int m = idx >> 4, c = idx & 15;
        float4 v  = *(const float4*)&Cs[m][4 * c];
        float4 bb = *(const float4*)&bias[colBase + 4 * c];
        v.x += bb.x; v.y += bb.y; v.z += bb.z; v.w += bb.w;
        *(float4*)&C[(size_t)(rowBase + m) * HD + colBase + 4 * c] = v;
    }
}

// ---------------------------------------------------------------------------
// Kernel 2: per-segment edge attention. One CTA per s = b*N + i.
// Edges for segment s are contiguous: e = s*DEG + d, d in [0,32).
// logits[d][h] = (Q[s] . (K[b*N+j] + Ek[r]))_h / sqrt(64)
// softmax over d per head; out[s] = sum_d attn[d][h(t)] * (V[b*N+j] + Ev[r])[t]
// ---------------------------------------------------------------------------
__global__ __launch_bounds__(384) void edge_attn(
    const int* __restrict__ ej, const int* __restrict__ er,
    const float* __restrict__ Ek, const float* __restrict__ Ev,
    float* __restrict__ out)
{
    const int s    = blockIdx.x;
    const int tid  = threadIdx.x;
    const int warp = tid >> 5;   // 0..11
    const int lane = tid & 31;

    __shared__ __align__(16) float qs[HD];
    __shared__ int js[DEG];
    __shared__ int rs[DEG];
    __shared__ float att[DEG][13];   // pad 13: stride coprime with 32 banks

    for (int t = tid; t < HD; t += 384) qs[t] = g_Q[(size_t)s * HD + t];
    if (tid < DEG) {
        int e = s * DEG + tid;
        js[tid] = (s & ~(NPB - 1)) + ej[e];   // b*N + j
        rs[tid] = er[e];
    }
    __syncthreads();

    // ---- logits: warp w handles edges d = w, w+12, w+24 ----
    // float4 i4 = u*32+lane covers elems 128u+4*lane..+3, all in head 2u+(lane>>4)
    const int hb = lane >> 4;
    const float4* qrow = (const float4*)qs;
    for (int d = warp; d < DEG; d += 12) {
        const float4* krow = (const float4*)(g_K + (size_t)js[d] * HD);
        const float4* erow = (const float4*)(Ek + (size_t)rs[d] * HD);
        float part[6];
        #pragma unroll
        for (int u = 0; u < 6; u++) {
            int i4 = u * 32 + lane;
            float4 k4 = krow[i4];
            float4 e4 = erow[i4];
            float4 q4 = qrow[i4];
            part[u] = q4.x * (k4.x + e4.x) + q4.y * (k4.y + e4.y)
                    + q4.z * (k4.z + e4.z) + q4.w * (k4.w + e4.w);
        }
        // reduce within each 16-lane half (head fixed per half)
        #pragma unroll
        for (int off = 8; off >= 1; off >>= 1)
            #pragma unroll
            for (int u = 0; u < 6; u++)
                part[u] += __shfl_xor_sync(0xffffffffu, part[u], off);
        if ((lane & 15) == 0) {
            #pragma unroll
            for (int u = 0; u < 6; u++)
                att[d][2 * u + hb] = part[u] * 0.125f;   // 1/sqrt(64)
        }
    }
    __syncthreads();

    // ---- softmax over the 32 edges: warp h owns head h, lane = d ----
    {
        float lg = att[lane][warp];
        float m = lg;
        #pragma unroll
        for (int off = 16; off >= 1; off >>= 1)
            m = fmaxf(m, __shfl_xor_sync(0xffffffffu, m, off));
        float ex = __expf(lg - m);
        float ssum = ex;
        #pragma unroll
        for (int off = 16; off >= 1; off >>= 1)
            ssum += __shfl_xor_sync(0xffffffffu, ssum, off);
        att[lane][warp] = ex / ssum;
    }
    __syncthreads();

    // ---- output: thread owns elems t=2*tid, 2*tid+1; head(t) == warp ----
    const int t = tid * 2;
    float2 acc = make_float2(0.f, 0.f);
    #pragma unroll 4
    for (int d = 0; d < DEG; d++) {
        float a = att[d][warp];   // smem broadcast
        float2 v  = *(const float2*)(g_V + (size_t)js[d] * HD + t);
        float2 e2 = *(const float2*)(Ev + (size_t)rs[d] * HD + t);
        acc.x += a * (v.x + e2.x);
        acc.y += a * (v.y + e2.y);
    }
    *(float2*)(out + (size_t)s * HD + t) = acc;
}

// ---------------------------------------------------------------------------
extern "C" void kernel_launch(void* const* d_in, const int* in_sizes, int n_in,
                              void* d_out, int out_size)
{
    const float* x  = (const float*)d_in[0];
    const int* edges = (const int*)d_in[1];
    const float* Wq = (const float*)d_in[2];
    const float* bq = (const float*)d_in[3];
    const float* Wk = (const float*)d_in[4];
    const float* bk = (const float*)d_in[5];
    const float* Wv = (const float*)d_in[6];
    const float* bv = (const float*)d_in[7];
    const float* Ek = (const float*)d_in[8];
    const float* Ev = (const float*)d_in[9];
    float* out = (float*)d_out;

    const size_t E = (size_t)in_sizes[1] / 4;

    dim3 ggrid(NNODES / BM, HD / BN, 3);
    qkv_gemm<<<ggrid, 128>>>(x, Wq, bq, Wk, bk, Wv, bv);
    edge_attn<<<NNODES, 384>>>(edges + 2 * E, edges + 3 * E, Ek, Ev, out);
}

// round 3
// speedup vs baseline: 1.0220x; 1.0220x over previous
#include <cuda_runtime.h>
#include <mma.h>
using namespace nvcuda;

#define NNODES 2048   // B*N
#define HD     768
#define NHEADS 12
#define DHEAD  64
#define DEG    32
#define NPB    256    // nodes per batch (N)

// Scratch for projections (no cudaMalloc allowed)
__device__ float g_Q[NNODES * HD];
__device__ float g_K[NNODES * HD];
__device__ float g_V[NNODES * HD];

// ---------------------------------------------------------------------------
// Kernel 1: QKV projection GEMM, C = X @ W + b   (tf32 wmma, fp32 accumulate)
// 128x128x32 CTA tile, 256 threads, 8 warps (32x64 warp tile, 2x4 frags),
// 2-stage cp.async double buffer. grid.z selects Q/K/V.
// ---------------------------------------------------------------------------
#define BM 128
#define BN 128
#define BK 32
#define PADA 36    // A row stride (floats): 144B, 16B multiple, avoids conflicts
#define PADB 132   // B row stride (floats): 528B, 16B multiple

#define A_BYTES (2 * BM * PADA * 4)                 // 36864
#define B_BYTES (2 * BK * PADB * 4)                 // 33792
#define GEMM_SMEM (A_BYTES + B_BYTES)               // 70656
// epilogue alias: Cs[BM][PADB] = 67584 <= GEMM_SMEM

__device__ __forceinline__ void cpa16(void* s, const void* g) {
    unsigned saddr = (unsigned)__cvta_generic_to_shared(s);
    asm volatile("cp.async.cg.shared.global [%0], [%1], 16;" :: "r"(saddr), "l"(g));
}

__global__ void __launch_bounds__(256) qkv_gemm(
    const float* __restrict__ X,
    const float* __restrict__ Wq, const float* __restrict__ bq,
    const float* __restrict__ Wk, const float* __restrict__ bk,
    const float* __restrict__ Wv, const float* __restrict__ bv)
{
    extern __shared__ __align__(16) unsigned char smem_raw[];
    float (*As)[BM][PADA] = reinterpret_cast<float (*)[BM][PADA]>(smem_raw);
    float (*Bs)[BK][PADB] = reinterpret_cast<float (*)[BK][PADB]>(smem_raw + A_BYTES);
    float (*Cs)[PADB]     = reinterpret_cast<float (*)[PADB]>(smem_raw);

    const int z = blockIdx.z;
    const float* W    = (z == 0) ? Wq : (z == 1) ? Wk : Wv;
    const float* bias = (z == 0) ? bq : (z == 1) ? bk : bv;
    float* C          = (z == 0) ? g_Q : (z == 1) ? g_K : g_V;

    const int tid  = threadIdx.x;
    const int warp = tid >> 5;
    const int wm   = (warp >> 1) * 32;   // 4 warp rows
    const int wn   = (warp & 1) * 64;    // 2 warp cols
    const int rowBase = blockIdx.x * BM;
    const int colBase = blockIdx.y * BN;

    wmma::fragment<wmma::accumulator, 16, 16, 8, float> cf[2][4];
    #pragma unroll
    for (int i = 0; i < 2; i++)
        #pragma unroll
        for (int j = 0; j < 4; j++)
            wmma::fill_fragment(cf[i][j], 0.0f);

    // A-chunk: 1024 16B chunks; 4/thread. row = idx>>3 (8 chunks/row), c = idx&7
    // B-chunk: 1024 16B chunks; 4/thread. row = idx>>5 (32 chunks/row), c = idx&31
    auto load_tiles = [&](int buf, int k0) {
        #pragma unroll
        for (int q = 0; q < 4; q++) {
            int idx = tid + 256 * q;
            int m = idx >> 3, c = idx & 7;
            cpa16(&As[buf][m][4 * c],
                  &X[(size_t)(rowBase + m) * HD + k0 + 4 * c]);
        }
        #pragma unroll
        for (int q = 0; q < 4; q++) {
            int idx = tid + 256 * q;
            int kk = idx >> 5, c = idx & 31;
            cpa16(&Bs[buf][kk][4 * c],
                  &W[(size_t)(k0 + kk) * HD + colBase + 4 * c]);
        }
        asm volatile("cp.async.commit_group;");
    };

    load_tiles(0, 0);

    const int NIT = HD / BK;   // 24
    for (int it = 0; it < NIT; ++it) {
        const int buf = it & 1;
        if (it + 1 < NIT) {
            load_tiles(buf ^ 1, (it + 1) * BK);
            asm volatile("cp.async.wait_group 1;");
        } else {
            asm volatile("cp.async.wait_group 0;");
        }
        __syncthreads();

        #pragma unroll
        for (int kk = 0; kk < BK; kk += 8) {
            wmma::fragment<wmma::matrix_a, 16, 16, 8, wmma::precision::tf32, wmma::row_major> a[2];
            wmma::fragment<wmma::matrix_b, 16, 16, 8, wmma::precision::tf32, wmma::row_major> b[4];
            wmma::load_matrix_sync(a[0], &As[buf][wm][kk], PADA);
            wmma::load_matrix_sync(a[1], &As[buf][wm + 16][kk], PADA);
            #pragma unroll
            for (int j = 0; j < 4; j++)
                wmma::load_matrix_sync(b[j], &Bs[buf][kk][wn + 16 * j], PADB);
            #pragma unroll
            for (int t = 0; t < a[0].num_elements; t++) {
                a[0].x[t] = wmma::__float_to_tf32(a[0].x[t]);
                a[1].x[t] = wmma::__float_to_tf32(a[1].x[t]);
            }
            #pragma unroll
            for (int j = 0; j < 4; j++)
                #pragma unroll
                for (int t = 0; t < b[j].num_elements; t++)
                    b[j].x[t] = wmma::__float_to_tf32(b[j].x[t]);
            #pragma unroll
            for (int i = 0; i < 2; i++)
                #pragma unroll
                for (int j = 0; j < 4; j++)
                    wmma::mma_sync(cf[i][j], a[i], b[j], cf[i][j]);
        }
        __syncthreads();
    }

    // Epilogue: stage to smem (aliases A/B buffers), add bias, float4 writes
    #pragma unroll
    for (int i = 0; i < 2; i++)
        #pragma unroll
        for (int j = 0; j < 4; j++)
            wmma::store_matrix_sync(&Cs[wm + 16 * i][wn + 16 * j], cf[i][j], PADB,
                                    wmma::mem_row_major);
    __syncthreads();
    #pragma unroll
    for (int q = 0; q < 16; q++) {
        int idx = tid + 256 * q;
        int m = idx >> 5, c = idx & 31;
        float4 v  = *(const float4*)&Cs[m][4 * c];
        float4 bb = *(const float4*)&bias[colBase + 4 * c];
        v.x += bb.x; v.y += bb.y; v.z += bb.z; v.w += bb.w;
        *(float4*)&C[(size_t)(rowBase + m) * HD + colBase + 4 * c] = v;
    }
}

// ---------------------------------------------------------------------------
// Kernel 2: per-segment edge attention. One CTA per s = b*N + i.
// Edges for segment s are contiguous: e = s*DEG + d, d in [0,32).
// logits[d][h] = (Q[s] . (K[b*N+j] + Ek[r]))_h / sqrt(64)
// softmax over d per head; out[s] = sum_d attn[d][h(t)] * (V[b*N+j] + Ev[r])[t]
// ---------------------------------------------------------------------------
__global__ __launch_bounds__(384) void edge_attn(
    const int* __restrict__ ej, const int* __restrict__ er,
    const float* __restrict__ Ek, const float* __restrict__ Ev,
    float* __restrict__ out)
{
    const int s    = blockIdx.x;
    const int tid  = threadIdx.x;
    const int warp = tid >> 5;   // 0..11
    const int lane = tid & 31;

    __shared__ __align__(16) float qs[HD];
    __shared__ int js[DEG];
    __shared__ int rs[DEG];
    __shared__ float att[DEG][13];   // pad 13: stride coprime with 32 banks

    for (int t = tid; t < HD; t += 384) qs[t] = g_Q[(size_t)s * HD + t];
    if (tid < DEG) {
        int e = s * DEG + tid;
        js[tid] = (s & ~(NPB - 1)) + ej[e];   // b*N + j
        rs[tid] = er[e];
    }
    __syncthreads();

    // ---- logits: warp w handles edges d = w, w+12, w+24 ----
    const int hb = lane >> 4;
    const float4* qrow = (const float4*)qs;
    for (int d = warp; d < DEG; d += 12) {
        const float4* krow = (const float4*)(g_K + (size_t)js[d] * HD);
        const float4* erow = (const float4*)(Ek + (size_t)rs[d] * HD);
        float part[6];
        #pragma unroll
        for (int u = 0; u < 6; u++) {
            int i4 = u * 32 + lane;
            float4 k4 = krow[i4];
            float4 e4 = erow[i4];
            float4 q4 = qrow[i4];
            part[u] = q4.x * (k4.x + e4.x) + q4.y * (k4.y + e4.y)
                    + q4.z * (k4.z + e4.z) + q4.w * (k4.w + e4.w);
        }
        #pragma unroll
        for (int off = 8; off >= 1; off >>= 1)
            #pragma unroll
            for (int u = 0; u < 6; u++)
                part[u] += __shfl_xor_sync(0xffffffffu, part[u], off);
        if ((lane & 15) == 0) {
            #pragma unroll
            for (int u = 0; u < 6; u++)
                att[d][2 * u + hb] = part[u] * 0.125f;   // 1/sqrt(64)
        }
    }
    __syncthreads();

    // ---- softmax over the 32 edges: warp h owns head h, lane = d ----
    {
        float lg = att[lane][warp];
        float m = lg;
        #pragma unroll
        for (int off = 16; off >= 1; off >>= 1)
            m = fmaxf(m, __shfl_xor_sync(0xffffffffu, m, off));
        float ex = __expf(lg - m);
        float ssum = ex;
        #pragma unroll
        for (int off = 16; off >= 1; off >>= 1)
            ssum += __shfl_xor_sync(0xffffffffu, ssum, off);
        att[lane][warp] = ex / ssum;
    }
    __syncthreads();

    // ---- output: thread owns elems t=2*tid, 2*tid+1; head(t) == warp ----
    const int t = tid * 2;
    float2 acc = make_float2(0.f, 0.f);
    #pragma unroll 4
    for (int d = 0; d < DEG; d++) {
        float a = att[d][warp];   // smem broadcast
        float2 v  = *(const float2*)(g_V + (size_t)js[d] * HD + t);
        float2 e2 = *(const float2*)(Ev + (size_t)rs[d] * HD + t);
        acc.x += a * (v.x + e2.x);
        acc.y += a * (v.y + e2.y);
    }
    *(float2*)(out + (size_t)s * HD + t) = acc;
}

// ---------------------------------------------------------------------------
extern "C" void kernel_launch(void* const* d_in, const int* in_sizes, int n_in,
                              void* d_out, int out_size)
{
    const float* x  = (const float*)d_in[0];
    const int* edges = (const int*)d_in[1];
    const float* Wq = (const float*)d_in[2];
    const float* bq = (const float*)d_in[3];
    const float* Wk = (const float*)d_in[4];
    const float* bk = (const float*)d_in[5];
    const float* Wv = (const float*)d_in[6];
    const float* bv = (const float*)d_in[7];
    const float* Ek = (const float*)d_in[8];
    const float* Ev = (const float*)d_in[9];
    float* out = (float*)d_out;

    const size_t E = (size_t)in_sizes[1] / 4;

    cudaFuncSetAttribute(qkv_gemm, cudaFuncAttributeMaxDynamicSharedMemorySize,
                         GEMM_SMEM);

    dim3 ggrid(NNODES / BM, HD / BN, 3);
    qkv_gemm<<<ggrid, 256, GEMM_SMEM>>>(x, Wq, bq, Wk, bk, Wv, bv);
    edge_attn<<<NNODES, 384>>>(edges + 2 * E, edges + 3 * E, Ek, Ev, out);
}

// round 6
// speedup vs baseline: 2.1672x; 2.1206x over previous
#include <cuda_runtime.h>
#include <cuda_fp16.h>
#include <mma.h>
#include <cstdint>
using namespace nvcuda;

#define NNODES 2048   // B*N
#define HD     768
#define DEG    32
#define NPB    256    // nodes per batch (N)

// Scratch (no cudaMalloc allowed)
__device__ float  g_Q[NNODES * HD];
__device__ float  g_K[NNODES * HD];
__device__ float  g_V[NNODES * HD];
__device__ __half g_Xh[NNODES * HD];
__device__ __half g_Wh[3 * HD * HD];

// ---------------------------------------------------------------------------
// Kernel 0: fp32 -> fp16 conversion for X and the three weight matrices.
// grid.y: 0 = X, 1..3 = Wq/Wk/Wv
// ---------------------------------------------------------------------------
__global__ __launch_bounds__(256) void cvt_f2h(
    const float* __restrict__ X,
    const float* __restrict__ Wq, const float* __restrict__ Wk,
    const float* __restrict__ Wv)
{
    const int z = blockIdx.y;
    const float* src;
    __half* dst;
    int n4;
    if (z == 0) { src = X; dst = g_Xh; n4 = NNODES * HD / 4; }
    else {
        src = (z == 1) ? Wq : (z == 2) ? Wk : Wv;
        dst = g_Wh + (size_t)(z - 1) * HD * HD;
        n4 = HD * HD / 4;
    }
    for (int i = blockIdx.x * blockDim.x + threadIdx.x; i < n4;
         i += gridDim.x * blockDim.x) {
        float4 v = ((const float4*)src)[i];
        __half2* d = (__half2*)dst;
        d[2 * i]     = __floats2half2_rn(v.x, v.y);
        d[2 * i + 1] = __floats2half2_rn(v.z, v.w);
    }
}

// ---------------------------------------------------------------------------
// Kernel 1: QKV projection GEMM, C = X @ W + b  (fp16 wmma, fp32 accumulate)
// 128x128x32 CTA tile, 256 threads, 8 warps (32x64 warp tile, 2x4 frags),
// 2-stage cp.async double buffer. grid.z selects Q/K/V.
// ---------------------------------------------------------------------------
#define BM 128
#define BN 128
#define BK 32
#define PA 40    // A row stride in halves: 80B, 16B multiple
#define PB 136   // B row stride in halves: 272B, 16B multiple
#define PC 132   // epilogue float stride

#define A_BYTES (2 * BM * PA * 2)                // 20480
#define B_BYTES (2 * BK * PB * 2)                // 17408
#define C_BYTES (BM * PC * 4)                    // 67584
#define GEMM_SMEM (C_BYTES)                      // epilogue aliases A/B

__device__ __forceinline__ void cpa16(void* s, const void* g) {
    unsigned sa = (unsigned)__cvta_generic_to_shared(s);
    asm volatile("cp.async.cg.shared.global [%0], [%1], 16;" :: "r"(sa), "l"(g));
}

__global__ void __launch_bounds__(256) qkv_gemm(
    const float* __restrict__ bq, const float* __restrict__ bk,
    const float* __restrict__ bv)
{
    extern __shared__ __align__(16) unsigned char smem_raw[];
    __half (*As)[BM][PA] = reinterpret_cast<__half (*)[BM][PA]>(smem_raw);
    __half (*Bs)[BK][PB] = reinterpret_cast<__half (*)[BK][PB]>(smem_raw + A_BYTES);
    float (*Cs)[PC]      = reinterpret_cast<float (*)[PC]>(smem_raw);

    const int z = blockIdx.z;
    const __half* W   = g_Wh + (size_t)z * HD * HD;
    const float* bias = (z == 0) ? bq : (z == 1) ? bk : bv;
    float* C          = (z == 0) ? g_Q : (z == 1) ? g_K : g_V;

    const int tid  = threadIdx.x;
    const int warp = tid >> 5;
    const int wm   = (warp >> 1) * 32;   // 4 warp rows
    const int wn   = (warp & 1) * 64;    // 2 warp cols
    const int rowBase = blockIdx.x * BM;
    const int colBase = blockIdx.y * BN;

    wmma::fragment<wmma::accumulator, 16, 16, 16, float> cf[2][4];
    #pragma unroll
    for (int i = 0; i < 2; i++)
        #pragma unroll
        for (int j = 0; j < 4; j++)
            wmma::fill_fragment(cf[i][j], 0.0f);

    // A tile: 128 rows x 32 halves (64B = 4 chunks/row) -> 512 chunks, 2/thread
    // B tile: 32 rows x 128 halves (256B = 16 chunks/row) -> 512 chunks, 2/thread
    auto load_tiles = [&](int buf, int k0) {
        #pragma unroll
        for (int q = 0; q < 2; q++) {
            int idx = tid + 256 * q;
            int m = idx >> 2, c = idx & 3;
            cpa16(&As[buf][m][8 * c],
                  &g_Xh[(size_t)(rowBase + m) * HD + k0 + 8 * c]);
        }
        #pragma unroll
        for (int q = 0; q < 2; q++) {
            int idx = tid + 256 * q;
            int kk = idx >> 4, c = idx & 15;
            cpa16(&Bs[buf][kk][8 * c],
                  &W[(size_t)(k0 + kk) * HD + colBase + 8 * c]);
        }
        asm volatile("cp.async.commit_group;");
    };

    load_tiles(0, 0);

    const int NIT = HD / BK;   // 24
    for (int it = 0; it < NIT; ++it) {
        const int buf = it & 1;
        if (it + 1 < NIT) {
            load_tiles(buf ^ 1, (it + 1) * BK);
            asm volatile("cp.async.wait_group 1;");
        } else {
            asm volatile("cp.async.wait_group 0;");
        }
        __syncthreads();

        #pragma unroll
        for (int kk = 0; kk < BK; kk += 16) {
            wmma::fragment<wmma::matrix_a, 16, 16, 16, __half, wmma::row_major> a[2];
            wmma::fragment<wmma::matrix_b, 16, 16, 16, __half, wmma::row_major> b[4];
            wmma::load_matrix_sync(a[0], &As[buf][wm][kk], PA);
            wmma::load_matrix_sync(a[1], &As[buf][wm + 16][kk], PA);
            #pragma unroll
            for (int j = 0; j < 4; j++)
                wmma::load_matrix_sync(b[j], &Bs[buf][kk][wn + 16 * j], PB);
            #pragma unroll
            for (int i = 0; i < 2; i++)
                #pragma unroll
                for (int j = 0; j < 4; j++)
                    wmma::mma_sync(cf[i][j], a[i], b[j], cf[i][j]);
        }
        __syncthreads();
    }

    // Epilogue: stage to smem (aliases A/B buffers), add bias, float4 writes
    #pragma unroll
    for (int i = 0; i < 2; i++)
        #pragma unroll
        for (int j = 0; j < 4; j++)
            wmma::store_matrix_sync(&Cs[wm + 16 * i][wn + 16 * j], cf[i][j], PC,
                                    wmma::mem_row_major);
    __syncthreads();
    #pragma unroll
    for (int q = 0; q < 16; q++) {
        int idx = tid + 256 * q;
        int m = idx >> 5, c = idx & 31;
        float4 v  = *(const float4*)&Cs[m][4 * c];
        float4 bb = *(const float4*)&bias[colBase + 4 * c];
        v.x += bb.x; v.y += bb.y; v.z += bb.z; v.w += bb.w;
        *(float4*)&C[(size_t)(rowBase + m) * HD + colBase + 4 * c] = v;
    }
}

// ---------------------------------------------------------------------------
// Kernel 2: per-segment edge attention. One CTA per s = b*N + i.
// min 3 CTAs/SM (caps regs at 56) -> occupancy 37.5% -> 56%.
// ---------------------------------------------------------------------------
__global__ __launch_bounds__(384, 3) void edge_attn(
    const int* __restrict__ ej, const int* __restrict__ er,
    const float* __restrict__ Ek, const float* __restrict__ Ev,
    float* __restrict__ out)
{
    const int s    = blockIdx.x;
    const int tid  = threadIdx.x;
    const int warp = tid >> 5;   // 0..11
    const int lane = tid & 31;

    __shared__ __align__(16) float qs[HD];
    __shared__ int js[DEG];
    __shared__ int rs[DEG];
    __shared__ float att[DEG][13];   // pad 13: stride coprime with 32 banks

    for (int t = tid; t < HD; t += 384) qs[t] = g_Q[(size_t)s * HD + t];
    if (tid < DEG) {
        int e = s * DEG + tid;
        js[tid] = (s & ~(NPB - 1)) + ej[e];   // b*N + j
        rs[tid] = er[e];
    }
    __syncthreads();

    // ---- logits: warp w handles edges d = w, w+12, w+24 ----
    const int hb = lane >> 4;
    const float4* qrow = (const float4*)qs;
    for (int d = warp; d < DEG; d += 12) {
        const float4* krow = (const float4*)(g_K + (size_t)js[d] * HD);
        const float4* erow = (const float4*)(Ek + (size_t)rs[d] * HD);
        float part[6];
        #pragma unroll
        for (int u = 0; u < 6; u++) {
            int i4 = u * 32 + lane;
            float4 k4 = krow[i4];
            float4 e4 = erow[i4];
            float4 q4 = qrow[i4];
            part[u] = q4.x * (k4.x + e4.x) + q4.y * (k4.y + e4.y)
                    + q4.z * (k4.z + e4.z) + q4.w * (k4.w + e4.w);
        }
        #pragma unroll
        for (int off = 8; off >= 1; off >>= 1)
            #pragma unroll
            for (int u = 0; u < 6; u++)
                part[u] += __shfl_xor_sync(0xffffffffu, part[u], off);
        if ((lane & 15) == 0) {
            #pragma unroll
            for (int u = 0; u < 6; u++)
                att[d][2 * u + hb] = part[u] * 0.125f;   // 1/sqrt(64)
        }
    }
    __syncthreads();

    // ---- softmax over the 32 edges: warp h owns head h, lane = d ----
    {
        float lg = att[lane][warp];
        float m = lg;
        #pragma unroll
        for (int off = 16; off >= 1; off >>= 1)
            m = fmaxf(m, __shfl_xor_sync(0xffffffffu, m, off));
        float ex = __expf(lg - m);
        float ssum = ex;
        #pragma unroll
        for (int off = 16; off >= 1; off >>= 1)
            ssum += __shfl_xor_sync(0xffffffffu, ssum, off);
        att[lane][warp] = ex / ssum;
    }
    __syncthreads();

    // ---- output: thread owns elems t=2*tid, 2*tid+1; head(t) == warp ----
    const int t = tid * 2;
    float2 acc = make_float2(0.f, 0.f);
    #pragma unroll 4
    for (int d = 0; d < DEG; d++) {
        float a = att[d][warp];   // smem broadcast
        float2 v  = *(const float2*)(g_V + (size_t)js[d] * HD + t);
        float2 e2 = *(const float2*)(Ev + (size_t)rs[d] * HD + t);
        acc.x += a * (v.x + e2.x);
        acc.y += a * (v.y + e2.y);
    }
    *(float2*)(out + (size_t)s * HD + t) = acc;
}

// ---------------------------------------------------------------------------
extern "C" void kernel_launch(void* const* d_in, const int* in_sizes, int n_in,
                              void* d_out, int out_size)
{
    const float* x  = (const float*)d_in[0];
    const int* edges = (const int*)d_in[1];
    const float* Wq = (const float*)d_in[2];
    const float* bq = (const float*)d_in[3];
    const float* Wk = (const float*)d_in[4];
    const float* bk = (const float*)d_in[5];
    const float* Wv = (const float*)d_in[6];
    const float* bv = (const float*)d_in[7];
    const float* Ek = (const float*)d_in[8];
    const float* Ev = (const float*)d_in[9];
    float* out = (float*)d_out;

    const size_t E = (size_t)in_sizes[1] / 4;

    cudaFuncSetAttribute(qkv_gemm, cudaFuncAttributeMaxDynamicSharedMemorySize,
                         GEMM_SMEM);

    cvt_f2h<<<dim3(192, 4), 256>>>(x, Wq, Wk, Wv);

    dim3 ggrid(NNODES / BM, HD / BN, 3);
    qkv_gemm<<<ggrid, 256, GEMM_SMEM>>>(bq, bk, bv);

    edge_attn<<<NNODES, 384>>>(edges + 2 * E, edges + 3 * E, Ek, Ev, out);
}

// round 7
// speedup vs baseline: 2.4142x; 1.1140x over previous
#include <cuda_runtime.h>
#include <cuda_fp16.h>
#include <mma.h>
#include <cstdint>
using namespace nvcuda;

#define NNODES 2048   // B*N
#define HD     768
#define DEG    32
#define NPB    256    // nodes per batch (N)
#define RREL   64

// Scratch (no cudaMalloc allowed)
__device__ float  g_Q[NNODES * HD];
__device__ __half g_Kh[NNODES * HD];
__device__ __half g_Vh[NNODES * HD];
__device__ __half g_Xh[NNODES * HD];
__device__ __half g_Wh[3 * HD * HD];
__device__ __half g_Ekh[RREL * HD];
__device__ __half g_Evh[RREL * HD];

// ---------------------------------------------------------------------------
// Kernel 0: fp32 -> fp16 conversion. One float4 per thread (no loop -> warp-
// level MLP instead of per-thread dependent chains).
// z: 0..3 = X quarters, 4..6 = Wq/Wk/Wv, 7 = Ek|Ev
// grid.x = 576 blocks x 256 thr; per-z bounds guard.
// ---------------------------------------------------------------------------
#define XQ4  (NNODES * HD / 16)     // 98304 float4 per X quarter
#define WQ4  (HD * HD / 4)          // 147456 float4 per weight
#define EQ4  (RREL * HD / 4)        // 12288 float4 per embedding table

__global__ __launch_bounds__(256) void cvt_f2h(
    const float* __restrict__ X,
    const float* __restrict__ Wq, const float* __restrict__ Wk,
    const float* __restrict__ Wv,
    const float* __restrict__ Ek, const float* __restrict__ Ev)
{
    const int z = blockIdx.y;
    const int idx = blockIdx.x * 256 + threadIdx.x;
    const float* src;
    __half2* dst;
    int n4, off;
    if (z < 4) {
        if (idx >= XQ4) return;
        src = X + (size_t)z * XQ4 * 4;
        dst = (__half2*)(g_Xh + (size_t)z * XQ4 * 4);
        n4 = XQ4;
    } else if (z < 7) {
        if (idx >= WQ4) return;
        src = (z == 4) ? Wq : (z == 5) ? Wk : Wv;
        dst = (__half2*)(g_Wh + (size_t)(z - 4) * HD * HD);
        n4 = WQ4;
    } else {
        if (idx >= 2 * EQ4) return;
        if (idx < EQ4) { src = Ek; dst = (__half2*)g_Ekh; off = idx; }
        else           { src = Ev; dst = (__half2*)g_Evh; off = idx - EQ4; }
        float4 v = ((const float4*)src)[off];
        dst[2 * off]     = __floats2half2_rn(v.x, v.y);
        dst[2 * off + 1] = __floats2half2_rn(v.z, v.w);
        return;
    }
    float4 v = ((const float4*)src)[idx];
    dst[2 * idx]     = __floats2half2_rn(v.x, v.y);
    dst[2 * idx + 1] = __floats2half2_rn(v.z, v.w);
}

// ---------------------------------------------------------------------------
// Kernel 1: QKV projection GEMM (fp16 wmma, fp32 acc). 128x128x32 CTA tile,
// 8 warps, cp.async double buffer. z=0 writes Q fp32; z=1/2 write K/V fp16.
// ---------------------------------------------------------------------------
#define BM 128
#define BN 128
#define BK 32
#define PA 40
#define PB 136
#define PC 132

#define A_BYTES (2 * BM * PA * 2)                // 20480
#define B_BYTES (2 * BK * PB * 2)                // 17408
#define C_BYTES (BM * PC * 4)                    // 67584
#define GEMM_SMEM (C_BYTES)

__device__ __forceinline__ void cpa16(void* s, const void* g) {
    unsigned sa = (unsigned)__cvta_generic_to_shared(s);
    asm volatile("cp.async.cg.shared.global [%0], [%1], 16;" :: "r"(sa), "l"(g));
}

__global__ void __launch_bounds__(256) qkv_gemm(
    const float* __restrict__ bq, const float* __restrict__ bk,
    const float* __restrict__ bv)
{
    extern __shared__ __align__(16) unsigned char smem_raw[];
    __half (*As)[BM][PA] = reinterpret_cast<__half (*)[BM][PA]>(smem_raw);
    __half (*Bs)[BK][PB] = reinterpret_cast<__half (*)[BK][PB]>(smem_raw + A_BYTES);
    float (*Cs)[PC]      = reinterpret_cast<float (*)[PC]>(smem_raw);

    const int z = blockIdx.z;
    const __half* W   = g_Wh + (size_t)z * HD * HD;
    const float* bias = (z == 0) ? bq : (z == 1) ? bk : bv;

    const int tid  = threadIdx.x;
    const int warp = tid >> 5;
    const int wm   = (warp >> 1) * 32;
    const int wn   = (warp & 1) * 64;
    const int rowBase = blockIdx.x * BM;
    const int colBase = blockIdx.y * BN;

    wmma::fragment<wmma::accumulator, 16, 16, 16, float> cf[2][4];
    #pragma unroll
    for (int i = 0; i < 2; i++)
        #pragma unroll
        for (int j = 0; j < 4; j++)
            wmma::fill_fragment(cf[i][j], 0.0f);

    auto load_tiles = [&](int buf, int k0) {
        #pragma unroll
        for (int q = 0; q < 2; q++) {
            int idx = tid + 256 * q;
            int m = idx >> 2, c = idx & 3;
            cpa16(&As[buf][m][8 * c],
                  &g_Xh[(size_t)(rowBase + m) * HD + k0 + 8 * c]);
        }
        #pragma unroll
        for (int q = 0; q < 2; q++) {
            int idx = tid + 256 * q;
            int kk = idx >> 4, c = idx & 15;
            cpa16(&Bs[buf][kk][8 * c],
                  &W[(size_t)(k0 + kk) * HD + colBase + 8 * c]);
        }
        asm volatile("cp.async.commit_group;");
    };

    load_tiles(0, 0);

    const int NIT = HD / BK;   // 24
    for (int it = 0; it < NIT; ++it) {
        const int buf = it & 1;
        if (it + 1 < NIT) {
            load_tiles(buf ^ 1, (it + 1) * BK);
            asm volatile("cp.async.wait_group 1;");
        } else {
            asm volatile("cp.async.wait_group 0;");
        }
        __syncthreads();

        #pragma unroll
        for (int kk = 0; kk < BK; kk += 16) {
            wmma::fragment<wmma::matrix_a, 16, 16, 16, __half, wmma::row_major> a[2];
            wmma::fragment<wmma::matrix_b, 16, 16, 16, __half, wmma::row_major> b[4];
            wmma::load_matrix_sync(a[0], &As[buf][wm][kk], PA);
            wmma::load_matrix_sync(a[1], &As[buf][wm + 16][kk], PA);
            #pragma unroll
            for (int j = 0; j < 4; j++)
                wmma::load_matrix_sync(b[j], &Bs[buf][kk][wn + 16 * j], PB);
            #pragma unroll
            for (int i = 0; i < 2; i++)
                #pragma unroll
                for (int j = 0; j < 4; j++)
                    wmma::mma_sync(cf[i][j], a[i], b[j], cf[i][j]);
        }
        __syncthreads();
    }

    #pragma unroll
    for (int i = 0; i < 2; i++)
        #pragma unroll
        for (int j = 0; j < 4; j++)
            wmma::store_matrix_sync(&Cs[wm + 16 * i][wn + 16 * j], cf[i][j], PC,
                                    wmma::mem_row_major);
    __syncthreads();

    if (z == 0) {
        #pragma unroll
        for (int q = 0; q < 16; q++) {
            int idx = tid + 256 * q;
            int m = idx >> 5, c = idx & 31;
            float4 v  = *(const float4*)&Cs[m][4 * c];
            float4 bb = *(const float4*)&bias[colBase + 4 * c];
            v.x += bb.x; v.y += bb.y; v.z += bb.z; v.w += bb.w;
            *(float4*)&g_Q[(size_t)(rowBase + m) * HD + colBase + 4 * c] = v;
        }
    } else {
        __half* Ch = (z == 1) ? g_Kh : g_Vh;
        #pragma unroll
        for (int q = 0; q < 16; q++) {
            int idx = tid + 256 * q;
            int m = idx >> 5, c = idx & 31;
            float4 v  = *(const float4*)&Cs[m][4 * c];
            float4 bb = *(const float4*)&bias[colBase + 4 * c];
            __half2 h0 = __floats2half2_rn(v.x + bb.x, v.y + bb.y);
            __half2 h1 = __floats2half2_rn(v.z + bb.z, v.w + bb.w);
            __half2* dst = (__half2*)&Ch[(size_t)(rowBase + m) * HD + colBase + 4 * c];
            dst[0] = h0;
            dst[1] = h1;
        }
    }
}

// ---------------------------------------------------------------------------
// Kernel 2: per-segment edge attention with fp16 gathers, fp32 math.
// ---------------------------------------------------------------------------
__global__ __launch_bounds__(384, 3) void edge_attn(
    const int* __restrict__ ej, const int* __restrict__ er,
    float* __restrict__ out)
{
    const int s    = blockIdx.x;
    const int tid  = threadIdx.x;
    const int warp = tid >> 5;   // 0..11
    const int lane = tid & 31;

    __shared__ __align__(16) float qs[HD];
    __shared__ int js[DEG];
    __shared__ int rs[DEG];
    __shared__ float att[DEG][13];

    for (int t = tid; t < HD; t += 384) qs[t] = g_Q[(size_t)s * HD + t];
    if (tid < DEG) {
        int e = s * DEG + tid;
        js[tid] = (s & ~(NPB - 1)) + ej[e];   // b*N + j
        rs[tid] = er[e];
    }
    __syncthreads();

    // ---- logits: warp w handles edges d = w, w+12, w+24 ----
    // uint4 i4 = u*32+lane covers elems 256u+8*lane..+7 -> head = 4u + (lane>>3)
    for (int d = warp; d < DEG; d += 12) {
        const uint4* krow = (const uint4*)(g_Kh + (size_t)js[d] * HD);
        const uint4* erow = (const uint4*)(g_Ekh + (size_t)rs[d] * HD);
        float part[3];
        #pragma unroll
        for (int u = 0; u < 3; u++) {
            int i4 = u * 32 + lane;
            uint4 k8 = krow[i4];
            uint4 e8 = erow[i4];
            const float* q = &qs[i4 * 8];
            float acc = 0.f;
            #pragma unroll
            for (int w = 0; w < 4; w++) {
                float2 kf = __half22float2(*(const __half2*)(((const uint32_t*)&k8) + w));
                float2 ef = __half22float2(*(const __half2*)(((const uint32_t*)&e8) + w));
                acc += q[2 * w] * (kf.x + ef.x) + q[2 * w + 1] * (kf.y + ef.y);
            }
            part[u] = acc;
        }
        #pragma unroll
        for (int off = 4; off >= 1; off >>= 1)
            #pragma unroll
            for (int u = 0; u < 3; u++)
                part[u] += __shfl_xor_sync(0xffffffffu, part[u], off);
        if ((lane & 7) == 0) {
            #pragma unroll
            for (int u = 0; u < 3; u++)
                att[d][4 * u + (lane >> 3)] = part[u] * 0.125f;   // 1/sqrt(64)
        }
    }
    __syncthreads();

    // ---- softmax over 32 edges: warp h owns head h, lane = d ----
    {
        float lg = att[lane][warp];
        float m = lg;
        #pragma unroll
        for (int off = 16; off >= 1; off >>= 1)
            m = fmaxf(m, __shfl_xor_sync(0xffffffffu, m, off));
        float ex = __expf(lg - m);
        float ssum = ex;
        #pragma unroll
        for (int off = 16; off >= 1; off >>= 1)
            ssum += __shfl_xor_sync(0xffffffffu, ssum, off);
        att[lane][warp] = ex / ssum;
    }
    __syncthreads();

    // ---- output: thread owns elems t=2*tid, 2*tid+1; head(t) == warp ----
    const int t = tid * 2;
    float2 acc = make_float2(0.f, 0.f);
    #pragma unroll 4
    for (int d = 0; d < DEG; d++) {
        float a = att[d][warp];
        float2 vf = __half22float2(*(const __half2*)(g_Vh + (size_t)js[d] * HD + t));
        float2 ef = __half22float2(*(const __half2*)(g_Evh + (size_t)rs[d] * HD + t));
        acc.x += a * (vf.x + ef.x);
        acc.y += a * (vf.y + ef.y);
    }
    *(float2*)(out + (size_t)s * HD + t) = acc;
}

// ---------------------------------------------------------------------------
extern "C" void kernel_launch(void* const* d_in, const int* in_sizes, int n_in,
                              void* d_out, int out_size)
{
    const float* x  = (const float*)d_in[0];
    const int* edges = (const int*)d_in[1];
    const float* Wq = (const float*)d_in[2];
    const float* bq = (const float*)d_in[3];
    const float* Wk = (const float*)d_in[4];
    const float* bk = (const float*)d_in[5];
    const float* Wv = (const float*)d_in[6];
    const float* bv = (const float*)d_in[7];
    const float* Ek = (const float*)d_in[8];
    const float* Ev = (const float*)d_in[9];
    float* out = (float*)d_out;

    const size_t E = (size_t)in_sizes[1] / 4;

    cudaFuncSetAttribute(qkv_gemm, cudaFuncAttributeMaxDynamicSharedMemorySize,
                         GEMM_SMEM);

    cvt_f2h<<<dim3(576, 8), 256>>>(x, Wq, Wk, Wv, Ek, Ev);

    dim3 ggrid(NNODES / BM, HD / BN, 3);
    qkv_gemm<<<ggrid, 256, GEMM_SMEM>>>(bq, bk, bv);

    edge_attn<<<NNODES, 384>>>(edges + 2 * E, edges + 3 * E, out);
}